// round 6
// baseline (speedup 1.0000x reference)
#include <cuda_runtime.h>

// Problem constants (B=512, F=512, max_depth=8 -> 255 splits, 511 nodes, 21 candidates)
#define BB 512
#define FF 512
#define NS 255
#define NN 511
#define NC 21
#define NB 148   // persistent blocks: <= SM count (GB300 has 152), all co-resident
#define NT 256

// Scratch (device globals; no allocation allowed)
__device__ float d_qnodeB[BB * NN];   // [b][n]
__device__ float d_qnodeT[NN * BB];   // [n][b] (coalesced per-node reads in phase 2)
__device__ float d_ga[NN * NC];       // [n][c]
__device__ float d_anode[NN];
__device__ unsigned d_bar_cnt = 0;
__device__ unsigned d_bar_gen = 0;    // monotonic across barriers & graph replays

// Software grid barrier. Safe because all NB blocks are co-resident (1/SM).
// atomicAdd(...,0) reads are L2-fresh; __threadfence (gpu scope) emits
// CCTL.IVALL on sm_103a -> flushes this SM's L1D, so data written by other
// blocks before the barrier is never read stale afterwards.
__device__ __forceinline__ void grid_barrier() {
    __syncthreads();
    if (threadIdx.x == 0) {
        __threadfence();                       // release my writes
        unsigned g = atomicAdd(&d_bar_gen, 0u);
        if (atomicAdd(&d_bar_cnt, 1u) == NB - 1u) {
            d_bar_cnt = 0u;
            __threadfence();
            atomicAdd(&d_bar_gen, 1u);
        } else {
            while (atomicAdd(&d_bar_gen, 0u) == g) __nanosleep(128);
        }
        __threadfence();                       // acquire + L1D flush
    }
    __syncthreads();
}

__device__ __forceinline__ void kadd(float& s, float& comp, float v) {
    float y = v - comp;
    float t = s + y;
    comp = (t - s) - y;
    s = t;
}

__device__ __forceinline__ float softmin_avg(const float* g) {
    float m = -1e30f;
#pragma unroll
    for (int c = 0; c < NC; ++c) m = fmaxf(m, -100.0f * g[c]);
    float num = 0.f, den = 0.f;
#pragma unroll
    for (int c = 0; c < NC; ++c) {
        float e = __expf(-100.0f * g[c] - m);
        num = fmaf((float)c * 0.05f, e, num);
        den += e;
    }
    return num / den;
}

// ---------------------------------------------------------------------------
// One fused persistent kernel: GEMM+qnode -> g_a -> PAV scan -> clip output.
// ---------------------------------------------------------------------------
__global__ __launch_bounds__(NT) void k_fused(const float* __restrict__ x,
                                              const float* __restrict__ W,
                                              const float* __restrict__ bias,
                                              float* __restrict__ out) {
    __shared__ __align__(16) float pool[12032];   // 47.0 KB static
    int bid = blockIdx.x;
    int tid = threadIdx.x;

    // ---------------- Phase 1: q_split = x@W + b, then q_node (blocks 0..127)
    if (bid < 128) {
        float* xs = pool;              // 2048 floats, interleaved [f][r]
        int rb = bid * 4;
        for (int i = tid; i < 4 * FF; i += NT) {
            int r = i >> 9;            // i / 512
            int f = i & 511;
            xs[f * 4 + r] = x[(rb + r) * FF + f];
        }
        __syncthreads();

        int s = tid;
        float a0 = 0.f, a1 = 0.f, a2 = 0.f, a3 = 0.f;
        if (s < NS) {
#pragma unroll 8
            for (int f = 0; f < FF; ++f) {
                float w = W[f * NS + s];
                float4 xv = *reinterpret_cast<const float4*>(&xs[f * 4]);
                a0 = fmaf(xv.x, w, a0);
                a1 = fmaf(xv.y, w, a1);
                a2 = fmaf(xv.z, w, a2);
                a3 = fmaf(xv.w, w, a3);
            }
            float bv = bias[s];
            a0 += bv; a1 += bv; a2 += bv; a3 += bv;
        }
        __syncthreads();               // xs reads done; reuse as q_split[4][256]
        if (s < NS) {
            xs[0 * 256 + s] = a0;
            xs[1 * 256 + s] = a1;
            xs[2 * 256 + s] = a2;
            xs[3 * 256 + s] = a3;
        }
        __syncthreads();

        // q_node[b][n] = min(1, min over ancestors p of (right-child? +q : -q))
        for (int idx = tid; idx < 4 * NN; idx += NT) {
            int r = idx / NN;
            int n = idx - r * NN;
            const float* qs = &xs[r * 256];
            float q = 1.0f;
            int a = n;
            while (a > 0) {
                int p = (a - 1) >> 1;
                float v = qs[p];
                q = fminf(q, (a == 2 * p + 2) ? v : -v);
                a = p;
            }
            d_qnodeB[(rb + r) * NN + n] = q;
            d_qnodeT[n * BB + rb + r] = q;
        }
    }
    grid_barrier();

    // ---------------- Phase 2: g_a[n][c]; nodes strided over blocks.
    {
        float* qrow = pool;            // 512
        float* red_s = pool + 512;     // 8*21
        float* red_c = pool + 512 + 8 * NC;
        int w = tid >> 5;
        int c = tid & 31;
        float ac = (float)c * 0.05f;
        for (int n = bid; n < NN; n += NB) {
            for (int i = tid; i < BB; i += NT) qrow[i] = d_qnodeT[n * BB + i];
            __syncthreads();
            if (c < NC) {
                float S = 0.f, C = 0.f;
                int b0 = w * 64;
#pragma unroll 4
                for (int b = b0; b < b0 + 64; ++b) {
                    float h = qrow[b] + 0.5f;
                    float d = ac - h;
                    if (ac <= h) kadd(S, C, d * d);
                }
                red_s[w * NC + c] = S;
                red_c[w * NC + c] = C;
            }
            __syncthreads();
            if (tid < NC) {
                float S = 0.f, C = 0.f;
#pragma unroll
                for (int ww = 0; ww < 8; ++ww) {
                    kadd(S, C, red_s[ww * NC + tid]);
                    C += red_c[ww * NC + tid];
                }
                float ssum = S - C;
                float acc = (float)tid * 0.05f;
                d_ga[n * NC + tid] = fmaf(0.5f * acc, acc, 0.5f * ssum);
            }
            __syncthreads();
        }
    }
    grid_barrier();

    // ---------------- Phase 3: PAV-like scan (block 0 only).
    //   n2g row i = (1-k_i) e_i + k_i e_par(i); incremental g_grp updates;
    //   fixed point once cond==false -> early exit (expected at iter 0).
    if (bid == 0) {
        float* gg = pool;                       // 10731
        float* agrp = pool + 10731;             // 511
        int* kk = (int*)(pool + 11242);         // 511
        float* r_val = pool + 11753;            // 8
        int* r_idx = (int*)(pool + 11761);      // 8
        int* sh_t = (int*)(pool + 11769);
        int* sh_done = (int*)(pool + 11770);

        for (int i = tid; i < NN * NC; i += NT) gg[i] = d_ga[i];
        for (int i = tid; i < NN; i += NT) kk[i] = 0;
        __syncthreads();
        for (int i = tid; i < NN; i += NT) agrp[i] = softmin_avg(&gg[i * NC]);
        __syncthreads();

        const unsigned FULL = 0xffffffffu;
        int i1 = tid, i2 = tid + 256;
        int p1 = (i1 > 0) ? ((i1 - 1) >> 1) : 0;
        int g1 = (p1 > 0) ? ((p1 - 1) >> 1) : 0;
        int p2 = (i2 - 1) >> 1;
        int g2 = (p2 > 0) ? ((p2 - 1) >> 1) : 0;
        float my_a1 = 0.f, my_a2 = 0.f;

        for (int iter = 0; iter < NN + 1; ++iter) {
            // viol for node i1 (always < NN)
            float k1 = (float)kk[i1];
            my_a1 = (1.0f - k1) * agrp[i1] + k1 * agrp[p1];
            float pa1;
            if (i1 == 0) pa1 = 1.0f;
            else {
                float kp = (float)kk[p1];
                pa1 = (1.0f - kp) * agrp[p1] + kp * agrp[g1];
            }
            float v = my_a1 - pa1;
            int ix = i1;
            // viol for node i2 (i2 < NN iff tid < 255)
            if (i2 < NN) {
                float k2 = (float)kk[i2];
                my_a2 = (1.0f - k2) * agrp[i2] + k2 * agrp[p2];
                float kp = (float)kk[p2];
                float pa2 = (1.0f - kp) * agrp[p2] + kp * agrp[g2];
                float v2 = my_a2 - pa2;
                if (v2 > v) { v = v2; ix = i2; }   // tie -> keep lower index i1
            }
#pragma unroll
            for (int off = 16; off > 0; off >>= 1) {
                float ov = __shfl_down_sync(FULL, v, off);
                int oi = __shfl_down_sync(FULL, ix, off);
                if (ov > v || (ov == v && oi < ix)) { v = ov; ix = oi; }
            }
            if ((tid & 31) == 0) { r_val[tid >> 5] = v; r_idx[tid >> 5] = ix; }
            __syncthreads();
            if (tid < 32) {
                float fv = (tid < 8) ? r_val[tid] : -1e30f;
                int fi = (tid < 8) ? r_idx[tid] : NN;
#pragma unroll
                for (int off = 4; off > 0; off >>= 1) {
                    float ov = __shfl_down_sync(FULL, fv, off);
                    int oi = __shfl_down_sync(FULL, fi, off);
                    if (ov > fv || (ov == fv && oi < fi)) { fv = ov; fi = oi; }
                }
                if (tid == 0) {
                    int cond = (fv <= 1e-8f) && (fi > 0);
                    *sh_done = !cond;
                    *sh_t = fi;
                    if (cond) kk[fi] += 1;   // merge: row fi gains (e_par - e_fi)
                }
            }
            __syncthreads();
            if (*sh_done) break;      // fixed point: remaining iterations no-ops
            if (iter == NN) break;    // final merge cannot affect returned a_node

            int t = *sh_t;
            int tp = (t - 1) >> 1;
            if (tid < NC) {
                gg[t * NC + tid] -= d_ga[t * NC + tid];
            } else if (tid >= 32 && tid < 32 + NC) {
                int c2 = tid - 32;
                gg[tp * NC + c2] += d_ga[t * NC + c2];
            }
            __syncwarp(FULL);
            if (tid == 0) agrp[t] = softmin_avg(&gg[t * NC]);
            if (tid == 32) agrp[tp] = softmin_avg(&gg[tp * NC]);
            __syncthreads();
        }

        d_anode[i1] = my_a1;
        if (i2 < NN) d_anode[i2] = my_a2;
    }
    grid_barrier();

    // ---------------- Phase 4: trajectory = clip(q_node, 0, a_node)
    {
        float* an = pool;   // 511 floats
        for (int i = tid; i < NN; i += NT) an[i] = d_anode[i];
        __syncthreads();
        const int TOT = BB * NN;
        for (int idx = bid * NT + tid; idx < TOT; idx += NB * NT) {
            int b = idx / NN;
            int n = idx - b * NN;
            float q = d_qnodeB[idx];
            out[idx] = fminf(fmaxf(q, 0.0f), an[n]);
        }
    }
}

extern "C" void kernel_launch(void* const* d_in, const int* in_sizes, int n_in,
                              void* d_out, int out_size) {
    const float* x = (const float*)d_in[0];
    const float* W = (const float*)d_in[1];
    const float* b = (const float*)d_in[2];
    // d_in[3] = max_depth (always 8; constants hardcoded)
    k_fused<<<NB, NT>>>(x, W, b, (float*)d_out);
}

// round 10
// speedup vs baseline: 1.1535x; 1.1535x over previous
#include <cuda_runtime.h>

// Problem constants (B=512, F=512, max_depth=8 -> 255 splits, 511 nodes, 21 candidates)
#define BB 512
#define FF 512
#define NS 255
#define NN 511
#define NC 21

// Scratch (device globals; no allocation allowed)
__device__ __align__(16) float d_qnodeB[BB * NN];   // [b][n]
__device__ float d_ga[NN * NC];       // [n][c]
__device__ float d_anode[NN];

// ---------------------------------------------------------------------------
// Kernel 1 (fused): q_split = x @ W + b (split-K x2), then q_node per row.
// grid 128, block 512. Threads [0,256) handle K-half 0, [256,512) K-half 1;
// thread's s = tid&255. 4 warps/SMSP for latency hiding; unroll 16 batches
// ~16 outstanding W loads. Partials combined via smem, then the q_node
// ancestor walk runs in-block on the shared q_split.
// ---------------------------------------------------------------------------
__global__ __launch_bounds__(512) void k_gemm_qnode(const float* __restrict__ x,
                                                    const float* __restrict__ W,
                                                    const float* __restrict__ bias) {
    __shared__ __align__(16) float xs[4 * FF];   // interleaved [f][r]; reused for q_split
    __shared__ float part[4][256];
    int rb = blockIdx.x * 4;
    for (int i = threadIdx.x; i < 4 * FF; i += 512) {
        int r = i >> 9;          // i / 512
        int f = i & 511;
        xs[f * 4 + r] = x[(rb + r) * FF + f];
    }
    __syncthreads();

    int half = threadIdx.x >> 8;     // 0 or 1 -> K range [half*256, half*256+256)
    int s = threadIdx.x & 255;
    float a0 = 0.f, a1 = 0.f, a2 = 0.f, a3 = 0.f;
    if (s < NS) {
        const float* Wp = W + (half << 8) * NS + s;
        const float4* xp = reinterpret_cast<const float4*>(xs) + (half << 8);
#pragma unroll 16
        for (int f = 0; f < 256; ++f) {
            float w = Wp[f * NS];
            float4 xv = xp[f];
            a0 = fmaf(xv.x, w, a0);
            a1 = fmaf(xv.y, w, a1);
            a2 = fmaf(xv.z, w, a2);
            a3 = fmaf(xv.w, w, a3);
        }
    }
    if (half == 1 && s < NS) {
        part[0][s] = a0; part[1][s] = a1; part[2][s] = a2; part[3][s] = a3;
    }
    __syncthreads();               // all xs reads done + partials visible
    if (half == 0 && s < NS) {
        float bv = bias[s];
        xs[0 * 256 + s] = a0 + part[0][s] + bv;
        xs[1 * 256 + s] = a1 + part[1][s] + bv;
        xs[2 * 256 + s] = a2 + part[2][s] + bv;
        xs[3 * 256 + s] = a3 + part[3][s] + bv;
    }
    __syncthreads();

    // q_node[b][n] = min(1, min over ancestors p of (right-child? +q : -q))
    for (int idx = threadIdx.x; idx < 4 * NN; idx += 512) {
        int r = idx / NN;
        int n = idx - r * NN;
        const float* qs = &xs[r * 256];
        float q = 1.0f;
        int a = n;
        while (a > 0) {
            int p = (a - 1) >> 1;
            float v = qs[p];
            q = fminf(q, (a == 2 * p + 2) ? v : -v);
            a = p;
        }
        d_qnodeB[(rb + r) * NN + n] = q;
    }
}

// ---------------------------------------------------------------------------
// Kernel 2: g_a[n][c] = 0.5*a_c^2 + 0.5 * sum_b [a_c <= q+0.5] (a_c-(q+0.5))^2
// grid 511 (node), block 128 (4 warps; warp w covers batch [w*128,(w+1)*128)).
// Each load is a single-address broadcast to the 21 active lanes; 8 Kahan-
// compensated float chains per warp for MLP (no FP64: B300 FP64 is slow).
// ---------------------------------------------------------------------------
__device__ __forceinline__ void kadd(float& s, float& comp, float v) {
    float y = v - comp;
    float t = s + y;
    comp = (t - s) - y;
    s = t;
}

__global__ __launch_bounds__(128) void k_ga() {
    __shared__ float red_s[4][NC];
    __shared__ float red_c[4][NC];
    int n = blockIdx.x;
    int w = threadIdx.x >> 5;
    int c = threadIdx.x & 31;
    const float* __restrict__ qb = &d_qnodeB[n];   // stride NN over batch
    float ac = (float)c * 0.05f;

    float s0 = 0, s1 = 0, s2 = 0, s3 = 0, s4 = 0, s5 = 0, s6 = 0, s7 = 0;
    float c0 = 0, c1 = 0, c2 = 0, c3 = 0, c4 = 0, c5 = 0, c6 = 0, c7 = 0;
    if (c < NC) {
        int b0 = w * 128;
        for (int b = b0; b < b0 + 128; b += 8) {
            float h0 = qb[(b + 0) * NN] + 0.5f;
            float h1 = qb[(b + 1) * NN] + 0.5f;
            float h2 = qb[(b + 2) * NN] + 0.5f;
            float h3 = qb[(b + 3) * NN] + 0.5f;
            float h4 = qb[(b + 4) * NN] + 0.5f;
            float h5 = qb[(b + 5) * NN] + 0.5f;
            float h6 = qb[(b + 6) * NN] + 0.5f;
            float h7 = qb[(b + 7) * NN] + 0.5f;
            float d0 = ac - h0, d1 = ac - h1, d2 = ac - h2, d3 = ac - h3;
            float d4 = ac - h4, d5 = ac - h5, d6 = ac - h6, d7 = ac - h7;
            if (ac <= h0) kadd(s0, c0, d0 * d0);
            if (ac <= h1) kadd(s1, c1, d1 * d1);
            if (ac <= h2) kadd(s2, c2, d2 * d2);
            if (ac <= h3) kadd(s3, c3, d3 * d3);
            if (ac <= h4) kadd(s4, c4, d4 * d4);
            if (ac <= h5) kadd(s5, c5, d5 * d5);
            if (ac <= h6) kadd(s6, c6, d6 * d6);
            if (ac <= h7) kadd(s7, c7, d7 * d7);
        }
        float S = 0.f, C = 0.f;
        kadd(S, C, s0); kadd(S, C, s1); kadd(S, C, s2); kadd(S, C, s3);
        kadd(S, C, s4); kadd(S, C, s5); kadd(S, C, s6); kadd(S, C, s7);
        C += ((c0 + c1) + (c2 + c3)) + ((c4 + c5) + (c6 + c7));
        red_s[w][c] = S;
        red_c[w][c] = C;
    }
    __syncthreads();
    if (threadIdx.x < NC) {
        int cc = threadIdx.x;
        float S = 0.f, C = 0.f;
        kadd(S, C, red_s[0][cc]); kadd(S, C, red_s[1][cc]);
        kadd(S, C, red_s[2][cc]); kadd(S, C, red_s[3][cc]);
        C += (red_c[0][cc] + red_c[1][cc]) + (red_c[2][cc] + red_c[3][cc]);
        float ssum = S - C;
        float acc = (float)cc * 0.05f;
        d_ga[n * NC + cc] = fmaf(0.5f * acc, acc, 0.5f * ssum);
    }
}

// ---------------------------------------------------------------------------
// Kernel 3: the PAV-like scan (k-counter reconstruction + early exit).
// ---------------------------------------------------------------------------
__device__ __forceinline__ float softmin_avg(const float* g) {
    float m = -1e30f;
#pragma unroll
    for (int c = 0; c < NC; ++c) m = fmaxf(m, -100.0f * g[c]);
    float num = 0.f, den = 0.f;
#pragma unroll
    for (int c = 0; c < NC; ++c) {
        float e = __expf(-100.0f * g[c] - m);
        num = fmaf((float)c * 0.05f, e, num);
        den += e;
    }
    return num / den;
}

__global__ __launch_bounds__(512) void k_scan() {
    __shared__ float gg[NN * NC];     // 42924 B
    __shared__ float agrp[NN];
    __shared__ int kk[NN];
    __shared__ float r_val[16];
    __shared__ int r_idx[16];
    __shared__ int sh_t;
    __shared__ int sh_done;

    int tid = threadIdx.x;
    for (int i = tid; i < NN * NC; i += 512) gg[i] = d_ga[i];
    if (tid < NN) kk[tid] = 0;
    __syncthreads();

    if (tid < NN) agrp[tid] = softmin_avg(&gg[tid * NC]);
    __syncthreads();

    const unsigned FULL = 0xffffffffu;
    int i = tid;
    int par = (i > 0) ? ((i - 1) >> 1) : 0;
    int gpar = (par > 0) ? ((par - 1) >> 1) : 0;
    float my_a = 0.0f;

    for (int iter = 0; iter < NN + 1; ++iter) {
        float viol = -1e30f;
        if (i < NN) {
            float ki = (float)kk[i];
            my_a = (1.0f - ki) * agrp[i] + ki * agrp[par];
            float pa;
            if (i == 0) {
                pa = 1.0f;
            } else {
                float kp = (float)kk[par];
                pa = (1.0f - kp) * agrp[par] + kp * agrp[gpar];
            }
            viol = my_a - pa;
        }
        float v = viol; int ix = i;
#pragma unroll
        for (int off = 16; off > 0; off >>= 1) {
            float ov = __shfl_down_sync(FULL, v, off);
            int oi = __shfl_down_sync(FULL, ix, off);
            if (ov > v || (ov == v && oi < ix)) { v = ov; ix = oi; }
        }
        if ((tid & 31) == 0) { r_val[tid >> 5] = v; r_idx[tid >> 5] = ix; }
        __syncthreads();
        if (tid < 32) {
            float fv = (tid < 16) ? r_val[tid] : -1e30f;
            int fi = (tid < 16) ? r_idx[tid] : NN;
#pragma unroll
            for (int off = 8; off > 0; off >>= 1) {
                float ov = __shfl_down_sync(FULL, fv, off);
                int oi = __shfl_down_sync(FULL, fi, off);
                if (ov > fv || (ov == fv && oi < fi)) { fv = ov; fi = oi; }
            }
            if (tid == 0) {
                int cond = (fv <= 1e-8f) && (fi > 0);
                sh_done = !cond;
                sh_t = fi;
                if (cond) kk[fi] += 1;   // merge: row fi gains (e_par - e_fi)
            }
        }
        __syncthreads();
        if (sh_done) break;       // fixed point: all remaining iterations no-ops
        if (iter == NN) break;    // last body's merge cannot affect returned a_node

        int t = sh_t;
        int tp = (t - 1) >> 1;
        if (tid < NC) {
            gg[t * NC + tid] -= d_ga[t * NC + tid];
        } else if (tid >= 32 && tid < 32 + NC) {
            int c2 = tid - 32;
            gg[tp * NC + c2] += d_ga[t * NC + c2];
        }
        __syncwarp(FULL);
        if (tid == 0) agrp[t] = softmin_avg(&gg[t * NC]);
        if (tid == 32) agrp[tp] = softmin_avg(&gg[tp * NC]);
        __syncthreads();
    }

    if (i < NN) d_anode[i] = my_a;
}

// ---------------------------------------------------------------------------
// Kernel 4: trajectory = clip(q_node, 0, a_node). float4 x 4-per-thread.
// BB*NN = 261632 = 4 * 65408; grid 256 x block 256 covers 65536 float4 slots.
// ---------------------------------------------------------------------------
__global__ __launch_bounds__(256) void k_out(float* __restrict__ out) {
    int v = blockIdx.x * blockDim.x + threadIdx.x;   // float4 index
    if (v < (BB * NN) / 4) {
        int idx = v * 4;
        float4 q = *reinterpret_cast<const float4*>(&d_qnodeB[idx]);
        int n0 = idx % NN;
        int n1 = (n0 + 1 == NN) ? 0 : n0 + 1;
        int n2 = (n1 + 1 == NN) ? 0 : n1 + 1;
        int n3 = (n2 + 1 == NN) ? 0 : n2 + 1;
        float4 r;
        r.x = fminf(fmaxf(q.x, 0.0f), d_anode[n0]);
        r.y = fminf(fmaxf(q.y, 0.0f), d_anode[n1]);
        r.z = fminf(fmaxf(q.z, 0.0f), d_anode[n2]);
        r.w = fminf(fmaxf(q.w, 0.0f), d_anode[n3]);
        *reinterpret_cast<float4*>(&out[idx]) = r;
    }
}

extern "C" void kernel_launch(void* const* d_in, const int* in_sizes, int n_in,
                              void* d_out, int out_size) {
    const float* x = (const float*)d_in[0];
    const float* W = (const float*)d_in[1];
    const float* b = (const float*)d_in[2];
    // d_in[3] = max_depth (always 8; constants hardcoded)

    k_gemm_qnode<<<BB / 4, 512>>>(x, W, b);
    k_ga<<<NN, 128>>>();
    k_scan<<<1, 512>>>();
    k_out<<<(BB * NN / 4 + 255) / 256, 256>>>((float*)d_out);
}